// round 1
// baseline (speedup 1.0000x reference)
#include <cuda_runtime.h>

// Problem constants (RAUMoE: B=8, P=4096, D=512, DOUT=512, E=8, K=2, L=3)
#define NTOK  32768
#define DIM   512
#define EXP   8
#define LHID  3

#define BM 128
#define BN 128
#define BK 32
#define TILES_M (NTOK / BM)   // 256 worst-case tiles per expert

// ---------------- scratch (device globals; no allocation allowed) ----------
__device__ int   g_cnt[EXP];
__device__ int   g_off[EXP];
__device__ int   g_cur[EXP];
__device__ int   g_eid[NTOK * 2];
__device__ float g_gw [NTOK * 2];
__device__ int   g_tok[NTOK * 2 + BM];
__device__ float g_wt [NTOK * 2 + BM];
__device__ int   g_slot[NTOK * 2];
// ping-pong activation buffers, compact layout [2N + pad][DIM]
__device__ __align__(16) float g_h0[(size_t)(NTOK * 2 + BM) * DIM];
__device__ __align__(16) float g_h1[(size_t)(NTOK * 2 + BM) * DIM];

// ---------------- small kernels -------------------------------------------
__global__ void zero_k() {
    if (threadIdx.x < EXP) g_cnt[threadIdx.x] = 0;
}

__global__ void gate1_k(const float* __restrict__ x,
                        const float* __restrict__ Wg,
                        const float* __restrict__ bg) {
    int n = blockIdx.x * 256 + threadIdx.x;
    float x0 = x[(long)n * DIM + DIM - 3];
    float x1 = x[(long)n * DIM + DIM - 2];
    float x2 = x[(long)n * DIM + DIM - 1];
    float g[EXP];
#pragma unroll
    for (int e = 0; e < EXP; e++)
        g[e] = fmaf(x0, Wg[e], fmaf(x1, Wg[EXP + e], fmaf(x2, Wg[2 * EXP + e], bg[e])));
    // top-1 (lowest index on ties, matching lax.top_k)
    int e0 = 0; float v0 = g[0];
#pragma unroll
    for (int e = 1; e < EXP; e++) if (g[e] > v0) { v0 = g[e]; e0 = e; }
    // top-2
    int e1 = -1; float v1 = -3.4e38f;
#pragma unroll
    for (int e = 0; e < EXP; e++) if (e != e0 && g[e] > v1) { v1 = g[e]; e1 = e; }
    float ew = expf(v1 - v0);
    float w0 = 1.0f / (1.0f + ew);
    float w1 = ew * w0;
    g_eid[2 * n] = e0; g_eid[2 * n + 1] = e1;
    g_gw [2 * n] = w0; g_gw [2 * n + 1] = w1;
    atomicAdd(&g_cnt[e0], 1);
    atomicAdd(&g_cnt[e1], 1);
}

__global__ void scan_k() {   // single thread, 8 entries
    int off = 0;
    for (int e = 0; e < EXP; e++) { g_off[e] = off; g_cur[e] = off; off += g_cnt[e]; }
}

__global__ void gate2_k() {
    int n = blockIdx.x * 256 + threadIdx.x;
#pragma unroll
    for (int j = 0; j < 2; j++) {
        int e = g_eid[2 * n + j];
        int pos = atomicAdd(&g_cur[e], 1);
        g_tok[pos] = n;
        g_wt[pos]  = g_gw[2 * n + j];
        g_slot[2 * n + j] = pos;
    }
}

// ---------------- grouped GEMM (tf32 mma.sync) -----------------------------
__device__ __forceinline__ unsigned f2tf(float f) {
    unsigned r;
    asm("cvt.rna.tf32.f32 %0, %1;" : "=r"(r) : "f"(f));
    return r;
}

// C[tile 128x128] = A[128x512] @ W_e[512x512] (+bias, opt relu, opt gate-weight)
// GATHER: A rows come via g_tok indirection (layer 0, reads x)
// FINAL:  multiply rows by g_wt and store to slot buffer (layer 3)
template <bool GATHER, bool RELU, bool FINAL>
__global__ __launch_bounds__(256) void moe_gemm(
    const float* __restrict__ Aparam, int asel,
    const float* __restrict__ Wbase, const float* __restrict__ Bbase,
    int osel, long wstride, long bstride)
{
    int e    = blockIdx.x / TILES_M;
    int tile = blockIdx.x % TILES_M;
    int cnt  = g_cnt[e];
    int t0   = tile * BM;
    if (t0 >= cnt) return;                 // inactive tile
    int row0 = g_off[e] + t0;
    int by   = blockIdx.y;

    const float* A  = GATHER ? Aparam : (asel ? g_h1 : g_h0);
    float*       Out = osel ? g_h1 : g_h0;
    const float* W  = Wbase + (long)e * wstride;
    const float* Bv = Bbase + (long)e * bstride;

    __shared__ unsigned As[BM][BK + 4];    // [m][k], pad 4 -> conflict-free frag loads
    __shared__ unsigned Bs[BK][BN + 8];    // [k][n], pad 8 -> conflict-free frag loads

    const int t = threadIdx.x;
    const int lane = t & 31, warp = t >> 5;
    const int wm = (warp & 3) * 32, wn = (warp >> 2) * 64;   // 4x2 warp grid
    const int gid = lane >> 2, tig = lane & 3;

    float acc[2][8][4];
#pragma unroll
    for (int a = 0; a < 2; a++)
#pragma unroll
        for (int b = 0; b < 8; b++)
#pragma unroll
            for (int c = 0; c < 4; c++) acc[a][b][c] = 0.f;

    for (int kt = 0; kt < DIM / BK; kt++) {
        // ---- A tile: 128 x 32 (1024 float4, 4 per thread) ----
#pragma unroll
        for (int j = 0; j < 4; j++) {
            int idx = t + j * 256;
            int m   = idx >> 3;
            int c4  = (idx & 7) << 2;
            float4 v = make_float4(0.f, 0.f, 0.f, 0.f);
            if (t0 + m < cnt) {
                long ar = GATHER ? (long)g_tok[row0 + m] : (long)(row0 + m);
                v = *reinterpret_cast<const float4*>(A + ar * DIM + kt * BK + c4);
            }
            As[m][c4 + 0] = f2tf(v.x); As[m][c4 + 1] = f2tf(v.y);
            As[m][c4 + 2] = f2tf(v.z); As[m][c4 + 3] = f2tf(v.w);
        }
        // ---- B tile: 32 x 128 ----
#pragma unroll
        for (int j = 0; j < 4; j++) {
            int idx = t + j * 256;
            int kr  = idx >> 5;
            int c4  = (idx & 31) << 2;
            float4 v = *reinterpret_cast<const float4*>(
                W + (long)(kt * BK + kr) * 512 + by * BN + c4);
            Bs[kr][c4 + 0] = f2tf(v.x); Bs[kr][c4 + 1] = f2tf(v.y);
            Bs[kr][c4 + 2] = f2tf(v.z); Bs[kr][c4 + 3] = f2tf(v.w);
        }
        __syncthreads();

#pragma unroll
        for (int ks = 0; ks < 4; ks++) {
            unsigned a[2][4], b[8][2];
#pragma unroll
            for (int mf = 0; mf < 2; mf++) {
                int r = wm + mf * 16 + gid;
                a[mf][0] = As[r    ][ks * 8 + tig];
                a[mf][1] = As[r + 8][ks * 8 + tig];
                a[mf][2] = As[r    ][ks * 8 + tig + 4];
                a[mf][3] = As[r + 8][ks * 8 + tig + 4];
            }
#pragma unroll
            for (int nf = 0; nf < 8; nf++) {
                b[nf][0] = Bs[ks * 8 + tig    ][wn + nf * 8 + gid];
                b[nf][1] = Bs[ks * 8 + tig + 4][wn + nf * 8 + gid];
            }
#pragma unroll
            for (int mf = 0; mf < 2; mf++)
#pragma unroll
                for (int nf = 0; nf < 8; nf++)
                    asm volatile(
                        "mma.sync.aligned.m16n8k8.row.col.f32.tf32.tf32.f32 "
                        "{%0,%1,%2,%3},{%4,%5,%6,%7},{%8,%9},{%0,%1,%2,%3};\n"
                        : "+f"(acc[mf][nf][0]), "+f"(acc[mf][nf][1]),
                          "+f"(acc[mf][nf][2]), "+f"(acc[mf][nf][3])
                        : "r"(a[mf][0]), "r"(a[mf][1]), "r"(a[mf][2]), "r"(a[mf][3]),
                          "r"(b[nf][0]), "r"(b[nf][1]));
        }
        __syncthreads();
    }

    // ---- epilogue: +bias, relu / gate-weight, store ----
#pragma unroll
    for (int nf = 0; nf < 8; nf++) {
        int col  = wn + nf * 8 + tig * 2;
        int gcol = by * BN + col;
        float bv0 = Bv[gcol], bv1 = Bv[gcol + 1];
#pragma unroll
        for (int mf = 0; mf < 2; mf++) {
#pragma unroll
            for (int h = 0; h < 2; h++) {
                int r = wm + mf * 16 + gid + h * 8;
                if (t0 + r < cnt) {
                    float v0 = acc[mf][nf][h * 2 + 0] + bv0;
                    float v1 = acc[mf][nf][h * 2 + 1] + bv1;
                    if (RELU) { v0 = fmaxf(v0, 0.f); v1 = fmaxf(v1, 0.f); }
                    if (FINAL) { float w = g_wt[row0 + r]; v0 *= w; v1 *= w; }
                    float2 o; o.x = v0; o.y = v1;
                    *reinterpret_cast<float2*>(Out + (long)(row0 + r) * 512 + gcol) = o;
                }
            }
        }
    }
}

// out[n] = y[slot0(n)] + y[slot1(n)]  (y lives in g_h1); overwrites all of d_out
__global__ void combine_k(float* __restrict__ out) {
    long i = (long)blockIdx.x * 256 + threadIdx.x;   // float4 index
    int n = (int)(i >> 7);
    int c = (int)(i & 127) << 2;
    int s0 = g_slot[2 * n], s1 = g_slot[2 * n + 1];
    const float4 a = *reinterpret_cast<const float4*>(g_h1 + (long)s0 * 512 + c);
    const float4 b = *reinterpret_cast<const float4*>(g_h1 + (long)s1 * 512 + c);
    float4 o;
    o.x = a.x + b.x; o.y = a.y + b.y; o.z = a.z + b.z; o.w = a.w + b.w;
    *reinterpret_cast<float4*>(out + i * 4) = o;
}

// ---------------- launch ----------------------------------------------------
extern "C" void kernel_launch(void* const* d_in, const int* in_sizes, int n_in,
                              void* d_out, int out_size) {
    const float* x  = (const float*)d_in[0];
    const float* Wg = (const float*)d_in[1];
    const float* bg = (const float*)d_in[2];
    const float* Wh = (const float*)d_in[3];
    const float* bh = (const float*)d_in[4];
    const float* Wo = (const float*)d_in[5];
    const float* bo = (const float*)d_in[6];
    float* out = (float*)d_out;

    zero_k<<<1, 32>>>();
    gate1_k<<<NTOK / 256, 256>>>(x, Wg, bg);
    scan_k<<<1, 1>>>();
    gate2_k<<<NTOK / 256, 256>>>();

    dim3 gg(EXP * TILES_M, DIM / BN);
    const long WS = (long)LHID * DIM * DIM;   // expert stride in Wh
    const long BS = (long)LHID * DIM;         // expert stride in bh

    // layer 0: gather x -> g_h0
    moe_gemm<true,  true,  false><<<gg, 256>>>(x,       0, Wh,                 bh,           0, WS, BS);
    // layer 1: g_h0 -> g_h1
    moe_gemm<false, true,  false><<<gg, 256>>>(nullptr, 0, Wh + 1L * DIM * DIM, bh + DIM,     1, WS, BS);
    // layer 2: g_h1 -> g_h0
    moe_gemm<false, true,  false><<<gg, 256>>>(nullptr, 1, Wh + 2L * DIM * DIM, bh + 2 * DIM, 0, WS, BS);
    // layer 3 (output, gate-weighted): g_h0 -> g_h1
    moe_gemm<false, false, true ><<<gg, 256>>>(nullptr, 0, Wo,                 bo,           1, (long)DIM * DIM, DIM);

    combine_k<<<NTOK * DIM / 4 / 256, 256>>>(out);
}

// round 7
// speedup vs baseline: 1.8961x; 1.8961x over previous
#include <cuda_runtime.h>
#include <cstdint>

// RAUMoE: B=8, P=4096, D=512, DOUT=512, E=8, K=2, L=3 (+1 output layer)
// Tensor path: legacy mma.sync tf32 (harness compiles via compute_103 PTX —
// tcgen05/'a'-features are rejected by ptxas, verified R5).
#define NTOK  32768
#define DIM   512
#define EXP   8
#define DD    (DIM * DIM)
#define BM    128
#define BN    128
#define BK    32
#define TILES_M (NTOK / BM)       // 256 worst-case tiles/expert
#define AP    36                  // u32 pitch (+4 pad): conflict-free ldmatrix rows
#define TILE_BYTES  (128 * AP * 4)      // 18432 per A or B tile
#define STAGE_BYTES (2 * TILE_BYTES)    // A + B
#define GEMM_SMEM   (2 * STAGE_BYTES)   // double buffer = 73728

// ---------------- scratch (device globals; no allocation allowed) ----------
__device__ int   g_cnt[EXP];
__device__ int   g_off[EXP];
__device__ int   g_cur[EXP];
__device__ int   g_eid[NTOK * 2];
__device__ float g_gw [NTOK * 2];
__device__ int   g_tok[NTOK * 2 + BM];
__device__ float g_wt [NTOK * 2 + BM];
__device__ int   g_slot[NTOK * 2];
__device__ __align__(16) float    g_h0[(size_t)(NTOK * 2 + BM) * DIM];
__device__ __align__(16) float    g_h1[(size_t)(NTOK * 2 + BM) * DIM];
// transposed tf32 weights: [layer 0..3][expert][n=512][k=512]  (n-major!)
__device__ __align__(16) unsigned g_wT[(size_t)4 * EXP * DD];

// ---------------- helpers ---------------------------------------------------
__device__ __forceinline__ unsigned f2tf(float f) {
    unsigned r; asm("cvt.rna.tf32.f32 %0, %1;" : "=r"(r) : "f"(f)); return r;
}
__device__ __forceinline__ float f2tf_f(float f) {
    return __uint_as_float(f2tf(f));
}
__device__ __forceinline__ uint32_t smem_u32(const void* p) {
    uint32_t a;
    asm("{ .reg .u64 t; cvta.to.shared.u64 t, %1; cvt.u32.u64 %0, t; }" : "=r"(a) : "l"(p));
    return a;
}
__device__ __forceinline__ void cp16(uint32_t dst, const void* src, int srcsz) {
    asm volatile("cp.async.cg.shared.global [%0], [%1], 16, %2;"
                 :: "r"(dst), "l"(src), "r"(srcsz) : "memory");
}
__device__ __forceinline__ void cp_commit() {
    asm volatile("cp.async.commit_group;" ::: "memory");
}
__device__ __forceinline__ void ldsm4(uint32_t& r0, uint32_t& r1, uint32_t& r2,
                                      uint32_t& r3, uint32_t addr) {
    asm volatile("ldmatrix.sync.aligned.m8n8.x4.shared.b16 {%0,%1,%2,%3}, [%4];"
                 : "=r"(r0), "=r"(r1), "=r"(r2), "=r"(r3) : "r"(addr));
}

// ---------------- small kernels ---------------------------------------------
__global__ void zero_k() { if (threadIdx.x < EXP) g_cnt[threadIdx.x] = 0; }

__global__ void gate1_k(const float* __restrict__ x,
                        const float* __restrict__ Wg,
                        const float* __restrict__ bg) {
    int n = blockIdx.x * 256 + threadIdx.x;
    int lane = threadIdx.x & 31;
    float x0 = x[(long)n * DIM + DIM - 3];
    float x1 = x[(long)n * DIM + DIM - 2];
    float x2 = x[(long)n * DIM + DIM - 1];
    float g[EXP];
#pragma unroll
    for (int e = 0; e < EXP; e++)
        g[e] = fmaf(x0, Wg[e], fmaf(x1, Wg[EXP + e], fmaf(x2, Wg[2 * EXP + e], bg[e])));
    int e0 = 0; float v0 = g[0];
#pragma unroll
    for (int e = 1; e < EXP; e++) if (g[e] > v0) { v0 = g[e]; e0 = e; }
    int e1 = -1; float v1 = -3.4e38f;
#pragma unroll
    for (int e = 0; e < EXP; e++) if (e != e0 && g[e] > v1) { v1 = g[e]; e1 = e; }
    float ew = expf(v1 - v0);
    float w0 = 1.0f / (1.0f + ew);
    g_eid[2 * n] = e0; g_eid[2 * n + 1] = e1;
    g_gw [2 * n] = w0; g_gw [2 * n + 1] = ew * w0;
#pragma unroll
    for (int j = 0; j < 2; j++) {
        int e = j ? e1 : e0;
        unsigned m = __match_any_sync(0xffffffffu, e);
        if ((m & ((1u << lane) - 1)) == 0) atomicAdd(&g_cnt[e], __popc(m));
    }
}

__global__ void scan_k() {
    int off = 0;
    for (int e = 0; e < EXP; e++) { g_off[e] = off; g_cur[e] = off; off += g_cnt[e]; }
}

__global__ void gate2_k() {
    int n = blockIdx.x * 256 + threadIdx.x;
    int lane = threadIdx.x & 31;
#pragma unroll
    for (int j = 0; j < 2; j++) {
        int e = g_eid[2 * n + j];
        unsigned m = __match_any_sync(0xffffffffu, e);
        int leader = __ffs(m) - 1;
        int rank = __popc(m & ((1u << lane) - 1));
        int base = 0;
        if (lane == leader) base = atomicAdd(&g_cur[e], __popc(m));
        base = __shfl_sync(0xffffffffu, base, leader);
        int pos = base + rank;
        g_tok[pos] = n;
        g_wt[pos]  = g_gw[2 * n + j];
        g_slot[2 * n + j] = pos;
    }
}

// weight transpose + tf32 convert: W[k][n] -> g_wT[(l,e)][n][k]
__global__ void wtrans_k(const float* __restrict__ Wh, const float* __restrict__ Wo) {
    __shared__ float s[32][33];
    int le = blockIdx.z, l = le >> 3, e = le & 7;
    const float* W = (l < 3) ? (Wh + ((size_t)e * 3 + l) * DD) : (Wo + (size_t)e * DD);
    unsigned* T = g_wT + (size_t)le * DD;
    int k0 = blockIdx.y * 32, n0 = blockIdx.x * 32;
    int tx = threadIdx.x, ty = threadIdx.y;
#pragma unroll
    for (int i = 0; i < 4; i++)
        s[ty + i * 8][tx] = W[(size_t)(k0 + ty + i * 8) * DIM + n0 + tx];
    __syncthreads();
#pragma unroll
    for (int i = 0; i < 4; i++)
        T[(size_t)(n0 + ty + i * 8) * DIM + k0 + tx] = f2tf(s[tx][ty + i * 8]);
}

// ---------------- grouped GEMM: tf32 mma.sync + cp.async + ldmatrix ---------
// C[128x128] = A[128x512] @ W_e slice, bias + relu/gate-weight epilogue.
// GATHER: A rows via g_tok (layer 0, manual cvt staging). Otherwise A is the
// activation buffer holding tf32-pre-rounded floats -> raw cp.async staging.
template <bool GATHER, bool RELU, bool FINAL>
__global__ __launch_bounds__(256, 2) void moe_gemm(
    const float* __restrict__ Ain, int asel, int layer,
    const float* __restrict__ Bbase, long bstride, int osel)
{
    int e    = blockIdx.x / TILES_M;
    int tile = blockIdx.x % TILES_M;
    int cnt  = g_cnt[e];
    int t0   = tile * BM;
    if (t0 >= cnt) return;
    int row0 = g_off[e] + t0;
    int by   = blockIdx.y;

    const float*    A   = GATHER ? Ain : (asel ? g_h1 : g_h0);
    float*          Out = osel ? g_h1 : g_h0;
    const unsigned* WT  = g_wT + ((size_t)layer * EXP + e) * DD;   // [n][k]
    const float*    Bv  = Bbase + (long)e * bstride;

    extern __shared__ char smem[];
    uint32_t s0 = smem_u32(smem);

    const int t = threadIdx.x, lane = t & 31, warp = t >> 5;
    const int wm = (warp & 3) * 32, wn = (warp >> 2) * 64;   // 4x2 warp grid
    const int gid = lane >> 2, tig = lane & 3;

    // ldmatrix per-thread byte offsets (within a tile)
    uint32_t a_off[2], b_off[4];
#pragma unroll
    for (int mf = 0; mf < 2; mf++)
        a_off[mf] = (uint32_t)((wm + mf * 16 + (lane & 15)) * AP * 4 + (lane >> 4) * 16);
#pragma unroll
    for (int nfp = 0; nfp < 4; nfp++)
        b_off[nfp] = (uint32_t)((wn + nfp * 16 + (lane & 7) + ((lane >> 4) & 1) * 8) * AP * 4
                                + ((lane >> 3) & 1) * 16);

    // staging indices: 4 x 16B segments each for A and B per thread per chunk
    int sm[4], sc4[4];
#pragma unroll
    for (int j = 0; j < 4; j++) { int s = t + j * 256; sm[j] = s >> 3; sc4[j] = s & 7; }

    float acc[2][8][4];
#pragma unroll
    for (int a = 0; a < 2; a++)
#pragma unroll
        for (int b = 0; b < 8; b++)
#pragma unroll
            for (int c = 0; c < 4; c++) acc[a][b][c] = 0.f;

    auto stage = [&](int kt) {
        int buf = kt & 1;
        uint32_t abase = s0 + buf * STAGE_BYTES;
        uint32_t bbase = abase + TILE_BYTES;
        // ---- A tile ----
        if (GATHER) {
#pragma unroll
            for (int j = 0; j < 4; j++) {
                int m = sm[j], c4 = sc4[j];
                float4 v = make_float4(0.f, 0.f, 0.f, 0.f);
                if (t0 + m < cnt) {
                    long ar = (long)g_tok[row0 + m];
                    v = *reinterpret_cast<const float4*>(A + ar * DIM + kt * BK + c4 * 4);
                }
                uint4 u; u.x = f2tf(v.x); u.y = f2tf(v.y); u.z = f2tf(v.z); u.w = f2tf(v.w);
                uint32_t dst = abase + (uint32_t)((m * AP + c4 * 4) * 4);
                *reinterpret_cast<uint4*>(smem + (dst - s0)) = u;
            }
        } else {
#pragma unroll
            for (int j = 0; j < 4; j++) {
                int m = sm[j], c4 = sc4[j];
                int live = (t0 + m < cnt) ? 16 : 0;
                const float* src = A + (long)(row0 + m) * DIM + kt * BK + c4 * 4;
                cp16(abase + (uint32_t)((m * AP + c4 * 4) * 4), src, live);
            }
        }
        // ---- B tile (always cp.async from pre-rounded g_wT) ----
#pragma unroll
        for (int j = 0; j < 4; j++) {
            int n = sm[j], c4 = sc4[j];
            const unsigned* src = WT + (size_t)(by * BN + n) * DIM + kt * BK + c4 * 4;
            cp16(bbase + (uint32_t)((n * AP + c4 * 4) * 4), src, 16);
        }
        cp_commit();
    };

    stage(0);
    stage(1);

    for (int kt = 0; kt < DIM / BK; kt++) {               // 16 chunks of K=32
        if (kt < 14) asm volatile("cp.async.wait_group 1;" ::: "memory");
        else         asm volatile("cp.async.wait_group 0;" ::: "memory");
        __syncthreads();

        int buf = kt & 1;
        uint32_t abase = s0 + buf * STAGE_BYTES;
        uint32_t bbase = abase + TILE_BYTES;

#pragma unroll
        for (int ks = 0; ks < 4; ks++) {
            uint32_t a[2][4], b[4][4];
#pragma unroll
            for (int mf = 0; mf < 2; mf++)
                ldsm4(a[mf][0], a[mf][1], a[mf][2], a[mf][3],
                      abase + a_off[mf] + ks * 32);
#pragma unroll
            for (int nfp = 0; nfp < 4; nfp++)
                ldsm4(b[nfp][0], b[nfp][1], b[nfp][2], b[nfp][3],
                      bbase + b_off[nfp] + ks * 32);
#pragma unroll
            for (int mf = 0; mf < 2; mf++)
#pragma unroll
                for (int nf = 0; nf < 8; nf++) {
                    int nfp = nf >> 1, hb = (nf & 1) * 2;
                    asm volatile(
                        "mma.sync.aligned.m16n8k8.row.col.f32.tf32.tf32.f32 "
                        "{%0,%1,%2,%3},{%4,%5,%6,%7},{%8,%9},{%0,%1,%2,%3};\n"
                        : "+f"(acc[mf][nf][0]), "+f"(acc[mf][nf][1]),
                          "+f"(acc[mf][nf][2]), "+f"(acc[mf][nf][3])
                        : "r"(a[mf][0]), "r"(a[mf][1]), "r"(a[mf][2]), "r"(a[mf][3]),
                          "r"(b[nfp][hb]), "r"(b[nfp][hb + 1]));
                }
        }
        __syncthreads();
        if (kt + 2 < DIM / BK) stage(kt + 2);
    }

    // ---- epilogue: +bias, relu/gate-weight, round-to-tf32 (non-final), store
#pragma unroll
    for (int nf = 0; nf < 8; nf++) {
        int col  = wn + nf * 8 + tig * 2;
        int gcol = by * BN + col;
        float bv0 = Bv[gcol], bv1 = Bv[gcol + 1];
#pragma unroll
        for (int mf = 0; mf < 2; mf++) {
#pragma unroll
            for (int h = 0; h < 2; h++) {
                int r = wm + mf * 16 + gid + h * 8;
                if (t0 + r < cnt) {
                    float v0 = acc[mf][nf][h * 2 + 0] + bv0;
                    float v1 = acc[mf][nf][h * 2 + 1] + bv1;
                    if (RELU) { v0 = fmaxf(v0, 0.f); v1 = fmaxf(v1, 0.f); }
                    if (FINAL) {
                        float w = g_wt[row0 + r]; v0 *= w; v1 *= w;
                    } else {
                        v0 = f2tf_f(v0); v1 = f2tf_f(v1);  // pre-round for cp.async
                    }
                    float2 o; o.x = v0; o.y = v1;
                    *reinterpret_cast<float2*>(Out + (long)(row0 + r) * DIM + gcol) = o;
                }
            }
        }
    }
}

// out[n] = y[slot0(n)] + y[slot1(n)]  (y in g_h1); overwrites all of d_out
__global__ void combine_k(float* __restrict__ out) {
    long i = (long)blockIdx.x * 256 + threadIdx.x;   // float4 index
    int n = (int)(i >> 7);
    int c = (int)(i & 127) << 2;
    int s0 = g_slot[2 * n], s1 = g_slot[2 * n + 1];
    const float4 a = *reinterpret_cast<const float4*>(g_h1 + (long)s0 * DIM + c);
    const float4 b = *reinterpret_cast<const float4*>(g_h1 + (long)s1 * DIM + c);
    float4 o;
    o.x = a.x + b.x; o.y = a.y + b.y; o.z = a.z + b.z; o.w = a.w + b.w;
    *reinterpret_cast<float4*>(out + i * 4) = o;
}

// ---------------- launch -----------------------------------------------------
extern "C" void kernel_launch(void* const* d_in, const int* in_sizes, int n_in,
                              void* d_out, int out_size) {
    const float* x  = (const float*)d_in[0];
    const float* Wg = (const float*)d_in[1];
    const float* bg = (const float*)d_in[2];
    const float* Wh = (const float*)d_in[3];
    const float* bh = (const float*)d_in[4];
    const float* Wo = (const float*)d_in[5];
    const float* bo = (const float*)d_in[6];
    float* out = (float*)d_out;

    cudaFuncSetAttribute(moe_gemm<true,  true,  false>,
                         cudaFuncAttributeMaxDynamicSharedMemorySize, GEMM_SMEM);
    cudaFuncSetAttribute(moe_gemm<false, true,  false>,
                         cudaFuncAttributeMaxDynamicSharedMemorySize, GEMM_SMEM);
    cudaFuncSetAttribute(moe_gemm<false, false, true >,
                         cudaFuncAttributeMaxDynamicSharedMemorySize, GEMM_SMEM);

    zero_k<<<1, 32>>>();
    gate1_k<<<NTOK / 256, 256>>>(x, Wg, bg);
    scan_k<<<1, 1>>>();
    gate2_k<<<NTOK / 256, 256>>>();
    wtrans_k<<<dim3(16, 16, 32), dim3(32, 8)>>>(Wh, Wo);

    dim3 gg(EXP * TILES_M, DIM / BN);
    // layer 0: gather x -> g_h0
    moe_gemm<true,  true,  false><<<gg, 256, GEMM_SMEM>>>(x,       0, 0, bh,           3 * DIM, 0);
    // layer 1: g_h0 -> g_h1
    moe_gemm<false, true,  false><<<gg, 256, GEMM_SMEM>>>(nullptr, 0, 1, bh + DIM,     3 * DIM, 1);
    // layer 2: g_h1 -> g_h0
    moe_gemm<false, true,  false><<<gg, 256, GEMM_SMEM>>>(nullptr, 1, 2, bh + 2 * DIM, 3 * DIM, 0);
    // layer 3 (output, gate-weighted): g_h0 -> g_h1
    moe_gemm<false, false, true ><<<gg, 256, GEMM_SMEM>>>(nullptr, 0, 3, bo,           DIM,     1);

    combine_k<<<NTOK * DIM / 4 / 256, 256>>>(out);
}